// round 10
// baseline (speedup 1.0000x reference)
#include <cuda_runtime.h>

#define BATCH 4
#define CH    64
#define HH    128
#define WW    128
#define HW    (HH*WW)
#define J18   18
#define CK    576   /* CH*9 */

// Device-global scratch
__device__ float  g_xt[BATCH*HW*CH];    // x NHWC [b][h][w][c]   16 MB
__device__ float  g_off[BATCH*HW*J18];  // offsets [b][h][w][j]  4.5 MB
__device__ float  g_wT[CK*CH];          // W [k=tap*64+c][o]     147 KB
__device__ int4   g_cidx[BATCH*HH*2*576];  // bilinear corner offsets  9.4 MB
__device__ float4 g_cwt [BATCH*HH*2*576];  // bilinear corner weights  9.4 MB

__device__ __forceinline__ void fma2(unsigned long long& a,
                                     unsigned long long b,
                                     unsigned long long c) {
    asm("fma.rn.f32x2 %0, %1, %2, %0;" : "+l"(a) : "l"(b), "l"(c));
}
__device__ __forceinline__ unsigned long long dup2(float v) {
    unsigned long long r;
    asm("mov.b64 %0, {%1,%1};" : "=l"(r) : "f"(v));
    return r;
}
__device__ __forceinline__ unsigned long long pack2(float a, float b) {
    unsigned long long r;
    asm("mov.b64 %0, {%1,%2};" : "=l"(r) : "f"(a), "f"(b));
    return r;
}
__device__ __forceinline__ void unpack2(unsigned long long v, float& a, float& b) {
    asm("mov.b64 {%0,%1}, %2;" : "=f"(a), "=f"(b) : "l"(v));
}

// ---------------------------------------------------------------------------
// Repack main weight: [o][c][tap] -> [k=tap*64+c][o]
// ---------------------------------------------------------------------------
__global__ void k_prep_wT(const float* __restrict__ weight) {
    int i = blockIdx.x * 256 + threadIdx.x;
    if (i >= CK * CH) return;
    int o = i & 63, k = i >> 6;
    int tap = k >> 6, c = k & 63;
    g_wT[k * 64 + o] = weight[(o * CH + c) * 9 + tap];
}

// ---------------------------------------------------------------------------
// NCHW -> NHWC transpose of x
// ---------------------------------------------------------------------------
__global__ void k_transpose(const float* __restrict__ x) {
    __shared__ float t[32][33];
    int b  = blockIdx.z;
    int c0 = blockIdx.y * 32;
    int p0 = blockIdx.x * 32;
    int tx = threadIdx.x, ty = threadIdx.y;   // 32 x 8
    const float* xb = x + (size_t)b * CH * HW;
#pragma unroll
    for (int i = 0; i < 4; i++)
        t[ty + i * 8][tx] = xb[(c0 + ty + i * 8) * HW + p0 + tx];
    __syncthreads();
    float* dst = g_xt + (size_t)b * HW * CH;
#pragma unroll
    for (int i = 0; i < 4; i++)
        dst[(p0 + ty + i * 8) * CH + c0 + tx] = t[tx][ty + i * 8];
}

// ---------------------------------------------------------------------------
// Offset conv: Conv2d(64 -> 18, 3x3, pad 1) on NCHW x, f32x2 accumulation.
// ---------------------------------------------------------------------------
__global__ void k_offconv(const float* __restrict__ x,
                          const float* __restrict__ w_off,
                          const float* __restrict__ b_off) {
    __shared__ __align__(16) float ws[CH * 9 * 20];
    int tid = threadIdx.y * 32 + threadIdx.x;
    for (int i = tid; i < CH * 9 * J18; i += 128) {
        int j = i % 18; int t = i / 18; int tap = t % 9; int c = t / 9;
        ws[(c * 9 + tap) * 20 + j] = w_off[(j * CH + c) * 9 + tap];
    }
    __syncthreads();

    int b = blockIdx.z;
    int h = blockIdx.y * 4 + threadIdx.y;
    int w = blockIdx.x * 32 + threadIdx.x;

    unsigned long long acc2[9];
#pragma unroll
    for (int q = 0; q < 9; q++)
        acc2[q] = pack2(__ldg(b_off + 2 * q), __ldg(b_off + 2 * q + 1));

    const float* xb = x + (size_t)b * CH * HW;
    for (int c = 0; c < CH; c++) {
        const float* xc = xb + c * HW;
#pragma unroll
        for (int r = 0; r < 3; r++) {
            int y = h + r - 1;
            if ((unsigned)y < (unsigned)HH) {
                const float* xr = xc + y * WW;
                float v0 = (w >= 1)      ? __ldg(xr + w - 1) : 0.f;
                float v1 =                 __ldg(xr + w);
                float v2 = (w < WW - 1)  ? __ldg(xr + w + 1) : 0.f;
                const float* wsr = ws + (c * 9 + r * 3) * 20;
#pragma unroll
                for (int s = 0; s < 3; s++) {
                    float val = (s == 0) ? v0 : ((s == 1) ? v1 : v2);
                    unsigned long long vd = dup2(val);
                    const double2* wp = (const double2*)(wsr + s * 20);
                    double2 p0 = wp[0], p1 = wp[1];
                    double2 p2 = wp[2], p3 = wp[3];
                    double   p4 = *(const double*)(wsr + s * 20 + 16);
                    fma2(acc2[0], vd, __double_as_longlong(p0.x));
                    fma2(acc2[1], vd, __double_as_longlong(p0.y));
                    fma2(acc2[2], vd, __double_as_longlong(p1.x));
                    fma2(acc2[3], vd, __double_as_longlong(p1.y));
                    fma2(acc2[4], vd, __double_as_longlong(p2.x));
                    fma2(acc2[5], vd, __double_as_longlong(p2.y));
                    fma2(acc2[6], vd, __double_as_longlong(p3.x));
                    fma2(acc2[7], vd, __double_as_longlong(p3.y));
                    fma2(acc2[8], vd, __double_as_longlong(p4));
                }
            }
        }
    }

    __syncthreads();
#pragma unroll
    for (int q = 0; q < 9; q++) {
        float a, bb;
        unpack2(acc2[q], a, bb);
        ws[threadIdx.y * 576 + threadIdx.x * 18 + 2 * q]     = a;
        ws[threadIdx.y * 576 + threadIdx.x * 18 + 2 * q + 1] = bb;
    }
    __syncthreads();
    for (int i = tid; i < 4 * 576; i += 128) {
        int row = i / 576, col = i % 576;
        int h2 = blockIdx.y * 4 + row;
        g_off[((size_t)b * HW + h2 * WW + blockIdx.x * 32) * 18 + col] = ws[row * 576 + col];
    }
}

// ---------------------------------------------------------------------------
// Coord precompute: bilinear corner indices + masked weights for every
// (b, h, strip, tap, px). Entry e = tap*64 + px within a 64-px strip.
// ---------------------------------------------------------------------------
__global__ void k_coords() {
    int strip = blockIdx.x & 1, h = blockIdx.x >> 1, b = blockIdx.y;
    int w0 = strip * 64;
    size_t base = ((size_t)(b * HH + h) * 2 + strip) * 576;
    for (int e = threadIdx.x; e < 576; e += 256) {
        int tap = e >> 6, px = e & 63;
        int w = w0 + px;
        const float* op = g_off + ((size_t)b * HW + h * WW + w) * 18 + tap * 2;
        float dy = __ldg(op), dx = __ldg(op + 1);
        float py  = (float)(h + tap / 3 - 1) + dy;
        float pxf = (float)(w + tap % 3 - 1) + dx;
        float fy = floorf(py), fx = floorf(pxf);
        int y0 = (int)fy, x0 = (int)fx;
        float ly = py - fy, lx = pxf - fx;
        float hy = 1.f - ly, hx = 1.f - lx;
        float my0 = ((unsigned)y0       < (unsigned)HH) ? 1.f : 0.f;
        float my1 = ((unsigned)(y0 + 1) < (unsigned)HH) ? 1.f : 0.f;
        float mx0 = ((unsigned)x0       < (unsigned)WW) ? 1.f : 0.f;
        float mx1 = ((unsigned)(x0 + 1) < (unsigned)WW) ? 1.f : 0.f;
        int y0c = min(max(y0, 0), HH - 1);
        int y1c = min(max(y0 + 1, 0), HH - 1);
        int x0c = min(max(x0, 0), WW - 1);
        int x1c = min(max(x0 + 1, 0), WW - 1);
        g_cidx[base + e] = make_int4((y0c * WW + x0c) * CH, (y0c * WW + x1c) * CH,
                                     (y1c * WW + x0c) * CH, (y1c * WW + x1c) * CH);
        g_cwt[base + e]  = make_float4(hy * hx * my0 * mx0, hy * lx * my0 * mx1,
                                       ly * hx * my1 * mx0, ly * lx * my1 * mx1);
    }
}

// ---------------------------------------------------------------------------
// Fused deform+GEMM. CTA = 64 o x 64 px (one 64-wide strip of one row h).
// 128 threads, smem = S only (32KB) -> 6 CTAs/SM (24 warps).
// Per tap: gather S_t[64 c][64 px DUP {s,s}] (XOR-swizzled, key = c&31 both
// sides), then GEMM partial: thread tile 8o x 4px, f32x2 pairs over (o,o+1):
// W pairs load directly, S pairs pre-duplicated -> zero dup movs.
// Coords come from g_cidx/g_cwt as warp-uniform broadcast LDGs.
// ---------------------------------------------------------------------------
#define SMEM_MAIN (64*128*4)   /* 32768 */

__global__ void __launch_bounds__(128) k_main(float* __restrict__ out) {
    extern __shared__ __align__(16) float sm[];
    float* sS = sm;                          // [64 c][64 px dup] 512B rows

    int b  = blockIdx.z;
    int h  = blockIdx.y;
    int w0 = blockIdx.x * 64;
    int tid  = threadIdx.x;
    int warp = tid >> 5, lane = tid & 31;

    const float* xt = g_xt + (size_t)b * HW * CH;
    size_t cbase = ((size_t)(b * HH + h) * 2 + blockIdx.x) * 576;
    const int4*   cidx = g_cidx + cbase;
    const float4* cwt  = g_cwt + cbase;

    int o_grp = tid & 7, px_grp = tid >> 3;     // 8 o-groups x 16 px-groups
    int o_base = o_grp * 8;
    unsigned long long acc[4][4];
#pragma unroll
    for (int p = 0; p < 4; p++)
#pragma unroll
        for (int j = 0; j < 4; j++) acc[p][j] = 0ULL;

    for (int tap = 0; tap < 9; tap++) {
        // ---- Gather: 32 tasks = 16 px-groups x 2 chan-halves ----
        for (int task = warp; task < 32; task += 4) {
            int chalf = task & 1, pxg = task >> 1;
            int c = chalf * 32 + lane;
            const float* xc = xt + c;
            float rv[4];
#pragma unroll
            for (int i = 0; i < 4; i++) {
                int e = tap * 64 + pxg * 4 + i;
                int4   ix = __ldg(cidx + e);
                float4 wt = __ldg(cwt + e);
                rv[i] = wt.x * __ldg(xc + ix.x) + wt.y * __ldg(xc + ix.y)
                      + wt.z * __ldg(xc + ix.z) + wt.w * __ldg(xc + ix.w);
            }
            float4* row = (float4*)(sS + c * 128);   // 32 slots of 16B
            int key = c & 31;
            row[(pxg * 2)     ^ key] = make_float4(rv[0], rv[0], rv[1], rv[1]);
            row[(pxg * 2 + 1) ^ key] = make_float4(rv[2], rv[2], rv[3], rv[3]);
        }
        __syncthreads();

        // ---- GEMM partial over 64 k (= channels of this tap) ----
        const float* wtap = g_wT + (size_t)(tap * 64) * 64 + o_base;
        int pp0 = px_grp * 2;
#pragma unroll 4
        for (int k = 0; k < 64; k++) {
            const ulonglong2* w8 = (const ulonglong2*)(wtap + k * 64);
            ulonglong2 wA = __ldg(w8);        // pairs (o0,o1),(o2,o3)
            ulonglong2 wB = __ldg(w8 + 1);    // pairs (o4,o5),(o6,o7)
            const ulonglong2* srow = (const ulonglong2*)(sS + k * 128);
            int key = k & 31;                 // matches store-side swizzle
            ulonglong2 sA = srow[pp0 ^ key];        // {s0,s0},{s1,s1}
            ulonglong2 sB = srow[(pp0 + 1) ^ key];  // {s2,s2},{s3,s3}
            fma2(acc[0][0], wA.x, sA.x); fma2(acc[0][1], wA.x, sA.y);
            fma2(acc[0][2], wA.x, sB.x); fma2(acc[0][3], wA.x, sB.y);
            fma2(acc[1][0], wA.y, sA.x); fma2(acc[1][1], wA.y, sA.y);
            fma2(acc[1][2], wA.y, sB.x); fma2(acc[1][3], wA.y, sB.y);
            fma2(acc[2][0], wB.x, sA.x); fma2(acc[2][1], wB.x, sA.y);
            fma2(acc[2][2], wB.x, sB.x); fma2(acc[2][3], wB.x, sB.y);
            fma2(acc[3][0], wB.y, sA.x); fma2(acc[3][1], wB.y, sA.y);
            fma2(acc[3][2], wB.y, sB.x); fma2(acc[3][3], wB.y, sB.y);
        }
        __syncthreads();
    }

    // ---- Epilogue: 8 output rows (o), 4 px each ----
    int w = w0 + px_grp * 4;
    float* ob = out + (((size_t)b * CH + o_base) * HH + h) * WW + w;
#pragma unroll
    for (int p = 0; p < 4; p++) {
        float e0, d0, e1, d1, e2, d2, e3, d3;
        unpack2(acc[p][0], e0, d0);
        unpack2(acc[p][1], e1, d1);
        unpack2(acc[p][2], e2, d2);
        unpack2(acc[p][3], e3, d3);
        *(float4*)(ob + (size_t)(2 * p) * HW)     = make_float4(e0, e1, e2, e3);
        *(float4*)(ob + (size_t)(2 * p + 1) * HW) = make_float4(d0, d1, d2, d3);
    }
}

// ---------------------------------------------------------------------------
extern "C" void kernel_launch(void* const* d_in, const int* in_sizes, int n_in,
                              void* d_out, int out_size) {
    const float* x      = (const float*)d_in[0];
    const float* w_off  = (const float*)d_in[1];
    const float* b_off  = (const float*)d_in[2];
    const float* weight = (const float*)d_in[3];
    float* out = (float*)d_out;

    cudaFuncSetAttribute(k_main, cudaFuncAttributeMaxDynamicSharedMemorySize,
                         SMEM_MAIN);

    k_prep_wT<<<(CK * CH + 255) / 256, 256>>>(weight);
    k_transpose<<<dim3(HW / 32, CH / 32, BATCH), dim3(32, 8)>>>(x);
    k_offconv<<<dim3(WW / 32, HH / 4, BATCH), dim3(32, 4)>>>(x, w_off, b_off);
    k_coords<<<dim3(2 * HH, BATCH), 256>>>();
    k_main<<<dim3(WW / 64, HH, BATCH), 128, SMEM_MAIN>>>(out);
}

// round 11
// speedup vs baseline: 1.6072x; 1.6072x over previous
#include <cuda_runtime.h>

#define BATCH 4
#define CH    64
#define HH    128
#define WW    128
#define HW    (HH*WW)
#define J18   18
#define CK    576   /* CH*9 */

// Device-global scratch
__device__ float g_xt[BATCH*HW*CH];    // x NHWC [b][h][w][c]   16 MB
__device__ float g_off[BATCH*HW*J18];  // offsets [b][h][w][j]  4.5 MB
__device__ float g_wT[CK*CH];          // W [k=tap*64+c][o]     147 KB

__device__ __forceinline__ void fma2(unsigned long long& a,
                                     unsigned long long b,
                                     unsigned long long c) {
    asm("fma.rn.f32x2 %0, %1, %2, %0;" : "+l"(a) : "l"(b), "l"(c));
}
__device__ __forceinline__ unsigned long long dup2(float v) {
    unsigned long long r;
    asm("mov.b64 %0, {%1,%1};" : "=l"(r) : "f"(v));
    return r;
}
__device__ __forceinline__ unsigned long long pack2(float a, float b) {
    unsigned long long r;
    asm("mov.b64 %0, {%1,%2};" : "=l"(r) : "f"(a), "f"(b));
    return r;
}
__device__ __forceinline__ void unpack2(unsigned long long v, float& a, float& b) {
    asm("mov.b64 {%0,%1}, %2;" : "=f"(a), "=f"(b) : "l"(v));
}

// ---------------------------------------------------------------------------
// Repack main weight: [o][c][tap] -> [k=tap*64+c][o]
// ---------------------------------------------------------------------------
__global__ void k_prep_wT(const float* __restrict__ weight) {
    int i = blockIdx.x * 256 + threadIdx.x;
    if (i >= CK * CH) return;
    int o = i & 63, k = i >> 6;
    int tap = k >> 6, c = k & 63;
    g_wT[k * 64 + o] = weight[(o * CH + c) * 9 + tap];
}

// ---------------------------------------------------------------------------
// NCHW -> NHWC transpose of x
// ---------------------------------------------------------------------------
__global__ void k_transpose(const float* __restrict__ x) {
    __shared__ float t[32][33];
    int b  = blockIdx.z;
    int c0 = blockIdx.y * 32;
    int p0 = blockIdx.x * 32;
    int tx = threadIdx.x, ty = threadIdx.y;   // 32 x 8
    const float* xb = x + (size_t)b * CH * HW;
#pragma unroll
    for (int i = 0; i < 4; i++)
        t[ty + i * 8][tx] = xb[(c0 + ty + i * 8) * HW + p0 + tx];
    __syncthreads();
    float* dst = g_xt + (size_t)b * HW * CH;
#pragma unroll
    for (int i = 0; i < 4; i++)
        dst[(p0 + ty + i * 8) * CH + c0 + tx] = t[tx][ty + i * 8];
}

// ---------------------------------------------------------------------------
// Offset conv: Conv2d(64 -> 18, 3x3, pad 1) on NCHW x, f32x2 accumulation.
// ---------------------------------------------------------------------------
__global__ void k_offconv(const float* __restrict__ x,
                          const float* __restrict__ w_off,
                          const float* __restrict__ b_off) {
    __shared__ __align__(16) float ws[CH * 9 * 20];
    int tid = threadIdx.y * 32 + threadIdx.x;
    for (int i = tid; i < CH * 9 * J18; i += 128) {
        int j = i % 18; int t = i / 18; int tap = t % 9; int c = t / 9;
        ws[(c * 9 + tap) * 20 + j] = w_off[(j * CH + c) * 9 + tap];
    }
    __syncthreads();

    int b = blockIdx.z;
    int h = blockIdx.y * 4 + threadIdx.y;
    int w = blockIdx.x * 32 + threadIdx.x;

    unsigned long long acc2[9];
#pragma unroll
    for (int q = 0; q < 9; q++)
        acc2[q] = pack2(__ldg(b_off + 2 * q), __ldg(b_off + 2 * q + 1));

    const float* xb = x + (size_t)b * CH * HW;
    for (int c = 0; c < CH; c++) {
        const float* xc = xb + c * HW;
#pragma unroll
        for (int r = 0; r < 3; r++) {
            int y = h + r - 1;
            if ((unsigned)y < (unsigned)HH) {
                const float* xr = xc + y * WW;
                float v0 = (w >= 1)      ? __ldg(xr + w - 1) : 0.f;
                float v1 =                 __ldg(xr + w);
                float v2 = (w < WW - 1)  ? __ldg(xr + w + 1) : 0.f;
                const float* wsr = ws + (c * 9 + r * 3) * 20;
#pragma unroll
                for (int s = 0; s < 3; s++) {
                    float val = (s == 0) ? v0 : ((s == 1) ? v1 : v2);
                    unsigned long long vd = dup2(val);
                    const double2* wp = (const double2*)(wsr + s * 20);
                    double2 p0 = wp[0], p1 = wp[1];
                    double2 p2 = wp[2], p3 = wp[3];
                    double   p4 = *(const double*)(wsr + s * 20 + 16);
                    fma2(acc2[0], vd, __double_as_longlong(p0.x));
                    fma2(acc2[1], vd, __double_as_longlong(p0.y));
                    fma2(acc2[2], vd, __double_as_longlong(p1.x));
                    fma2(acc2[3], vd, __double_as_longlong(p1.y));
                    fma2(acc2[4], vd, __double_as_longlong(p2.x));
                    fma2(acc2[5], vd, __double_as_longlong(p2.y));
                    fma2(acc2[6], vd, __double_as_longlong(p3.x));
                    fma2(acc2[7], vd, __double_as_longlong(p3.y));
                    fma2(acc2[8], vd, __double_as_longlong(p4));
                }
            }
        }
    }

    __syncthreads();
#pragma unroll
    for (int q = 0; q < 9; q++) {
        float a, bb;
        unpack2(acc2[q], a, bb);
        ws[threadIdx.y * 576 + threadIdx.x * 18 + 2 * q]     = a;
        ws[threadIdx.y * 576 + threadIdx.x * 18 + 2 * q + 1] = bb;
    }
    __syncthreads();
    for (int i = tid; i < 4 * 576; i += 128) {
        int row = i / 576, col = i % 576;
        int h2 = blockIdx.y * 4 + row;
        g_off[((size_t)b * HW + h2 * WW + blockIdx.x * 32) * 18 + col] = ws[row * 576 + col];
    }
}

// ---------------------------------------------------------------------------
// Fused deform+GEMM. CTA = 64 o x 64 px (one 64-wide strip of one row h).
// 256 threads, thread tile 4o x 4px. smem: S 32KB + coords 18KB = 50KB
// -> 4 CTAs/SM = 32 warps (67% occ). Per tap: gather S_t[64 c][64 px DUP
// {s,s}] (XOR swizzle key = c&31 / k&31 on both sides), then GEMM partial:
// W ulonglong2 = 2 (o,o+1) f32x2 pairs loaded directly, S pre-duplicated
// -> zero dup movs.
// ---------------------------------------------------------------------------
#define NPT 576   /* 9 taps x 64 px */
#define SMEM_MAIN (64*128*4 + NPT*16 + NPT*16)   /* 51200 */

__global__ void __launch_bounds__(256, 4) k_main(float* __restrict__ out) {
    extern __shared__ __align__(16) float sm[];
    float*  sS   = sm;                          // [64 c][64 px dup] 512B rows
    int4*   sIdx = (int4*)(sm + 64 * 128);      // [576]
    float4* sWt  = (float4*)(sm + 64 * 128 + NPT * 4);

    int b  = blockIdx.z;
    int h  = blockIdx.y;
    int w0 = blockIdx.x * 64;
    int tid  = threadIdx.x;
    int warp = tid >> 5, lane = tid & 31;

    const float* xt = g_xt + (size_t)b * HW * CH;

    // ---- Precompute bilinear coords: entry e = tap*64 + px ----
    for (int e = tid; e < NPT; e += 256) {
        int tap = e >> 6, px = e & 63;
        int w = w0 + px;
        const float* op = g_off + ((size_t)b * HW + h * WW + w) * 18 + tap * 2;
        float dy = __ldg(op), dx = __ldg(op + 1);
        float py  = (float)(h + tap / 3 - 1) + dy;
        float pxf = (float)(w + tap % 3 - 1) + dx;
        float fy = floorf(py), fx = floorf(pxf);
        int y0 = (int)fy, x0 = (int)fx;
        float ly = py - fy, lx = pxf - fx;
        float hy = 1.f - ly, hx = 1.f - lx;
        float my0 = ((unsigned)y0       < (unsigned)HH) ? 1.f : 0.f;
        float my1 = ((unsigned)(y0 + 1) < (unsigned)HH) ? 1.f : 0.f;
        float mx0 = ((unsigned)x0       < (unsigned)WW) ? 1.f : 0.f;
        float mx1 = ((unsigned)(x0 + 1) < (unsigned)WW) ? 1.f : 0.f;
        int y0c = min(max(y0, 0), HH - 1);
        int y1c = min(max(y0 + 1, 0), HH - 1);
        int x0c = min(max(x0, 0), WW - 1);
        int x1c = min(max(x0 + 1, 0), WW - 1);
        sIdx[e] = make_int4((y0c * WW + x0c) * CH, (y0c * WW + x1c) * CH,
                            (y1c * WW + x0c) * CH, (y1c * WW + x1c) * CH);
        sWt[e]  = make_float4(hy * hx * my0 * mx0, hy * lx * my0 * mx1,
                              ly * hx * my1 * mx0, ly * lx * my1 * mx1);
    }
    __syncthreads();

    int o_grp = tid & 15, px_grp = tid >> 4;    // 16 o-groups x 16 px-groups
    int o_base = o_grp * 4;
    unsigned long long acc[2][4];
#pragma unroll
    for (int p = 0; p < 2; p++)
#pragma unroll
        for (int j = 0; j < 4; j++) acc[p][j] = 0ULL;

    for (int tap = 0; tap < 9; tap++) {
        // ---- Gather: 32 tasks = 16 px-groups x 2 chan-halves, 8 warps ----
        for (int task = warp; task < 32; task += 8) {
            int chalf = task & 1, pxg = task >> 1;
            int c = chalf * 32 + lane;
            const float* xc = xt + c;
            float rv[4];
#pragma unroll
            for (int i = 0; i < 4; i++) {
                int e = tap * 64 + pxg * 4 + i;
                int4   ix = sIdx[e];
                float4 wt = sWt[e];
                rv[i] = wt.x * __ldg(xc + ix.x) + wt.y * __ldg(xc + ix.y)
                      + wt.z * __ldg(xc + ix.z) + wt.w * __ldg(xc + ix.w);
            }
            float4* row = (float4*)(sS + c * 128);   // 32 slots of 16B
            int key = c & 31;
            row[(pxg * 2)     ^ key] = make_float4(rv[0], rv[0], rv[1], rv[1]);
            row[(pxg * 2 + 1) ^ key] = make_float4(rv[2], rv[2], rv[3], rv[3]);
        }
        __syncthreads();

        // ---- GEMM partial over 64 k (= channels of this tap) ----
        const float* wtap = g_wT + (size_t)(tap * 64) * 64 + o_base;
        int pp0 = px_grp * 2;
#pragma unroll 8
        for (int k = 0; k < 64; k++) {
            ulonglong2 wA = __ldg((const ulonglong2*)(wtap + k * 64));
            const ulonglong2* srow = (const ulonglong2*)(sS + k * 128);
            int key = k & 31;                 // matches store-side swizzle
            ulonglong2 sA = srow[pp0 ^ key];        // {s0,s0},{s1,s1}
            ulonglong2 sB = srow[(pp0 + 1) ^ key];  // {s2,s2},{s3,s3}
            fma2(acc[0][0], wA.x, sA.x); fma2(acc[0][1], wA.x, sA.y);
            fma2(acc[0][2], wA.x, sB.x); fma2(acc[0][3], wA.x, sB.y);
            fma2(acc[1][0], wA.y, sA.x); fma2(acc[1][1], wA.y, sA.y);
            fma2(acc[1][2], wA.y, sB.x); fma2(acc[1][3], wA.y, sB.y);
        }
        __syncthreads();
    }

    // ---- Epilogue: 4 output rows (o), 4 px each ----
    int w = w0 + px_grp * 4;
    float* ob = out + (((size_t)b * CH + o_base) * HH + h) * WW + w;
#pragma unroll
    for (int p = 0; p < 2; p++) {
        float e0, d0, e1, d1, e2, d2, e3, d3;
        unpack2(acc[p][0], e0, d0);
        unpack2(acc[p][1], e1, d1);
        unpack2(acc[p][2], e2, d2);
        unpack2(acc[p][3], e3, d3);
        *(float4*)(ob + (size_t)(2 * p) * HW)     = make_float4(e0, e1, e2, e3);
        *(float4*)(ob + (size_t)(2 * p + 1) * HW) = make_float4(d0, d1, d2, d3);
    }
}

// ---------------------------------------------------------------------------
extern "C" void kernel_launch(void* const* d_in, const int* in_sizes, int n_in,
                              void* d_out, int out_size) {
    const float* x      = (const float*)d_in[0];
    const float* w_off  = (const float*)d_in[1];
    const float* b_off  = (const float*)d_in[2];
    const float* weight = (const float*)d_in[3];
    float* out = (float*)d_out;

    cudaFuncSetAttribute(k_main, cudaFuncAttributeMaxDynamicSharedMemorySize,
                         SMEM_MAIN);

    k_prep_wT<<<(CK * CH + 255) / 256, 256>>>(weight);
    k_transpose<<<dim3(HW / 32, CH / 32, BATCH), dim3(32, 8)>>>(x);
    k_offconv<<<dim3(WW / 32, HH / 4, BATCH), dim3(32, 4)>>>(x, w_off, b_off);
    k_main<<<dim3(WW / 64, HH, BATCH), 256, SMEM_MAIN>>>(out);
}